// round 12
// baseline (speedup 1.0000x reference)
#include <cuda_runtime.h>

#define D 128
#define D4 (D / 4)              // 32 float4 per row
#define THREADS 128
#define CCHUNKS 4               // column chunks per segment (32 cols each)
#define CF4 (D4 / CCHUNKS)      // 8 float4 columns per chunk
#define RGROUPS (THREADS / CF4) // 16 row groups
#define MAX_B 1024              // dataset: B = 1024 segments

__global__ __launch_bounds__(THREADS, 8)
void seg_mean_persist(const float* __restrict__ x,
                      const int* __restrict__ lens,
                      float* __restrict__ out,
                      int B, int ntasks)
{
    const int tid  = threadIdx.x;
    const int lane = tid & 31;
    const int wid  = tid >> 5;

    // ---- one-time: exclusive scan of lens into smem soff[0..B] ----
    __shared__ int soff[MAX_B + 1];
    __shared__ int wsum[4];
    {
        const int K = (B + THREADS - 1) / THREADS;   // elems per thread (8 @ B=1024)
        int v[8];
        int tsum = 0;
        #pragma unroll
        for (int k = 0; k < 8; k++) {
            int i = tid * K + k;
            int e = (k < K && i < B) ? __ldg(&lens[i]) : 0;
            v[k] = tsum;          // prefix before element k
            tsum += e;
        }
        // inclusive warp scan of thread sums
        int inc = tsum;
        #pragma unroll
        for (int off = 1; off < 32; off <<= 1) {
            int u = __shfl_up_sync(0xFFFFFFFFu, inc, off);
            if (lane >= off) inc += u;
        }
        if (lane == 31) wsum[wid] = inc;
        __syncthreads();
        int wadd = 0;
        #pragma unroll
        for (int w = 0; w < 4; w++) wadd += (w < wid) ? wsum[w] : 0;
        const int excl = wadd + inc - tsum;   // exclusive prefix of this thread
        #pragma unroll
        for (int k = 0; k < 8; k++) {
            int i = tid * K + k;
            if (k < K && i < B) soff[i] = excl + v[k];
        }
        if (tid == THREADS - 1) soff[B] = excl + tsum;
        __syncthreads();
    }

    __shared__ float4 sred[RGROUPS][CF4];
    const int csub = tid & (CF4 - 1);
    const int rg   = tid >> 3;

    // ---- persistent task loop: task = (segment, column chunk) ----
    for (int task = blockIdx.x; task < ntasks; task += gridDim.x) {
        const int b = task >> 2;
        const int c = task & (CCHUNKS - 1);
        const int start = soff[b];
        const int len   = soff[b + 1] - start;

        const float4* __restrict__ xv =
            reinterpret_cast<const float4*>(x) + (size_t)start * D4;
        const int cg = c * CF4 + csub;

        float4 a0 = make_float4(0.f, 0.f, 0.f, 0.f);
        float4 a1 = a0, a2 = a0, a3 = a0;

        int r = rg;
        for (; r + 7 * RGROUPS < len; r += 8 * RGROUPS) {
            float4 v0 = xv[(size_t)(r + 0 * RGROUPS) * D4 + cg];
            float4 v1 = xv[(size_t)(r + 1 * RGROUPS) * D4 + cg];
            float4 v2 = xv[(size_t)(r + 2 * RGROUPS) * D4 + cg];
            float4 v3 = xv[(size_t)(r + 3 * RGROUPS) * D4 + cg];
            float4 v4 = xv[(size_t)(r + 4 * RGROUPS) * D4 + cg];
            float4 v5 = xv[(size_t)(r + 5 * RGROUPS) * D4 + cg];
            float4 v6 = xv[(size_t)(r + 6 * RGROUPS) * D4 + cg];
            float4 v7 = xv[(size_t)(r + 7 * RGROUPS) * D4 + cg];
            a0.x += v0.x; a0.y += v0.y; a0.z += v0.z; a0.w += v0.w;
            a1.x += v1.x; a1.y += v1.y; a1.z += v1.z; a1.w += v1.w;
            a2.x += v2.x; a2.y += v2.y; a2.z += v2.z; a2.w += v2.w;
            a3.x += v3.x; a3.y += v3.y; a3.z += v3.z; a3.w += v3.w;
            a0.x += v4.x; a0.y += v4.y; a0.z += v4.z; a0.w += v4.w;
            a1.x += v5.x; a1.y += v5.y; a1.z += v5.z; a1.w += v5.w;
            a2.x += v6.x; a2.y += v6.y; a2.z += v6.z; a2.w += v6.w;
            a3.x += v7.x; a3.y += v7.y; a3.z += v7.z; a3.w += v7.w;
        }
        for (; r < len; r += RGROUPS) {
            float4 v = xv[(size_t)r * D4 + cg];
            a0.x += v.x; a0.y += v.y; a0.z += v.z; a0.w += v.w;
        }
        a0.x += a1.x + a2.x + a3.x;
        a0.y += a1.y + a2.y + a3.y;
        a0.z += a1.z + a2.z + a3.z;
        a0.w += a1.w + a2.w + a3.w;

        sred[rg][csub] = a0;
        __syncthreads();

        if (tid < CF4) {
            float4 s = sred[0][tid];
            #pragma unroll
            for (int g = 1; g < RGROUPS; g++) {
                float4 v = sred[g][tid];
                s.x += v.x; s.y += v.y; s.z += v.z; s.w += v.w;
            }
            const float inv = 1.0f / (float)len;
            float4 o = make_float4(s.x * inv, s.y * inv, s.z * inv, s.w * inv);
            reinterpret_cast<float4*>(out)[(size_t)b * D4 + c * CF4 + tid] = o;
        }
        __syncthreads();   // protect sred before next task
    }
}

extern "C" void kernel_launch(void* const* d_in, const int* in_sizes, int n_in,
                              void* d_out, int out_size)
{
    const float* x    = (const float*)d_in[0];
    const int*   lens = (const int*)d_in[1];
    float*       out  = (float*)d_out;
    const int B = in_sizes[1];
    const int ntasks = B * CCHUNKS;

    int grid = 148 * 8;
    if (grid > ntasks) grid = ntasks;
    seg_mean_persist<<<grid, THREADS>>>(x, lens, out, B, ntasks);
}

// round 13
// speedup vs baseline: 1.0259x; 1.0259x over previous
#include <cuda_runtime.h>

#define D 128
#define D4 (D / 4)              // 32 float4 per row
#define THREADS 128
#define CCHUNKS 4               // column chunks per segment (32 cols each)
#define CF4 (D4 / CCHUNKS)      // 8 float4 columns per chunk
#define RGROUPS (THREADS / CF4) // 16 row groups

__global__ __launch_bounds__(THREADS, 8)
void seg_mean_kernel(const float* __restrict__ x,
                     const int* __restrict__ lens,
                     float* __restrict__ out)
{
    const int b   = blockIdx.x >> 2;            // segment
    const int c   = blockIdx.x & (CCHUNKS - 1); // column chunk
    const int tid = threadIdx.x;
    const int lane = tid & 31;
    const int wid  = tid >> 5;

    // ---- segment start = sum(lens[0..b)): strided loads + shfl reduce ----
    __shared__ int ws[4];
    int psum = 0;
    for (int i = tid; i < b; i += THREADS) psum += __ldg(&lens[i]);
    #pragma unroll
    for (int off = 16; off > 0; off >>= 1)
        psum += __shfl_down_sync(0xFFFFFFFFu, psum, off);
    if (lane == 0) ws[wid] = psum;
    __syncthreads();
    const int start = ws[0] + ws[1] + ws[2] + ws[3];
    const int len   = __ldg(&lens[b]);

    // ---- accumulate columns [8c, 8c+8) (float4 units) over all rows ----
    const float4* __restrict__ xv =
        reinterpret_cast<const float4*>(x) + (size_t)start * D4;
    const int cg = c * CF4 + (tid & (CF4 - 1));  // float4 column 0..31
    const int rg = tid >> 3;                     // row group 0..15

    float4 a0 = make_float4(0.f, 0.f, 0.f, 0.f);
    float4 a1 = a0, a2 = a0, a3 = a0;

    int r = rg;
    // 8 independent in-flight LDG.128 per thread, 128 rows/iter per CTA
    for (; r + 7 * RGROUPS < len; r += 8 * RGROUPS) {
        float4 v0 = xv[(size_t)(r + 0 * RGROUPS) * D4 + cg];
        float4 v1 = xv[(size_t)(r + 1 * RGROUPS) * D4 + cg];
        float4 v2 = xv[(size_t)(r + 2 * RGROUPS) * D4 + cg];
        float4 v3 = xv[(size_t)(r + 3 * RGROUPS) * D4 + cg];
        float4 v4 = xv[(size_t)(r + 4 * RGROUPS) * D4 + cg];
        float4 v5 = xv[(size_t)(r + 5 * RGROUPS) * D4 + cg];
        float4 v6 = xv[(size_t)(r + 6 * RGROUPS) * D4 + cg];
        float4 v7 = xv[(size_t)(r + 7 * RGROUPS) * D4 + cg];
        a0.x += v0.x; a0.y += v0.y; a0.z += v0.z; a0.w += v0.w;
        a1.x += v1.x; a1.y += v1.y; a1.z += v1.z; a1.w += v1.w;
        a2.x += v2.x; a2.y += v2.y; a2.z += v2.z; a2.w += v2.w;
        a3.x += v3.x; a3.y += v3.y; a3.z += v3.z; a3.w += v3.w;
        a0.x += v4.x; a0.y += v4.y; a0.z += v4.z; a0.w += v4.w;
        a1.x += v5.x; a1.y += v5.y; a1.z += v5.z; a1.w += v5.w;
        a2.x += v6.x; a2.y += v6.y; a2.z += v6.z; a2.w += v6.w;
        a3.x += v7.x; a3.y += v7.y; a3.z += v7.z; a3.w += v7.w;
    }
    for (; r < len; r += RGROUPS) {
        float4 v = xv[(size_t)r * D4 + cg];
        a0.x += v.x; a0.y += v.y; a0.z += v.z; a0.w += v.w;
    }
    a0.x += a1.x + a2.x + a3.x;
    a0.y += a1.y + a2.y + a3.y;
    a0.z += a1.z + a2.z + a3.z;
    a0.w += a1.w + a2.w + a3.w;

    // ---- reduce 16 row-groups per column in smem ----
    __shared__ float4 sred[RGROUPS][CF4];
    sred[rg][tid & (CF4 - 1)] = a0;
    __syncthreads();

    if (tid < CF4) {
        float4 s = sred[0][tid];
        #pragma unroll
        for (int g = 1; g < RGROUPS; g++) {
            float4 v = sred[g][tid];
            s.x += v.x; s.y += v.y; s.z += v.z; s.w += v.w;
        }
        const float inv = 1.0f / (float)len;
        float4 o = make_float4(s.x * inv, s.y * inv, s.z * inv, s.w * inv);
        reinterpret_cast<float4*>(out)[(size_t)b * D4 + c * CF4 + tid] = o;
    }
}

extern "C" void kernel_launch(void* const* d_in, const int* in_sizes, int n_in,
                              void* d_out, int out_size)
{
    const float* x    = (const float*)d_in[0];
    const int*   lens = (const int*)d_in[1];
    float*       out  = (float*)d_out;
    const int B = in_sizes[1];

    seg_mean_kernel<<<B * CCHUNKS, THREADS>>>(x, lens, out);
}

// round 14
// speedup vs baseline: 1.0463x; 1.0199x over previous
#include <cuda_runtime.h>

#define D 128
#define D4 (D / 4)              // 32 float4 per row
#define THREADS 256
#define NWARPS (THREADS / 32)   // 8
#define CCHUNKS 2               // column chunks per segment (64 cols each)
#define CF4 (D4 / CCHUNKS)      // 16 float4 columns per chunk
#define RGROUPS (THREADS / CF4) // 16 row groups

__global__ __launch_bounds__(THREADS, 4)
void seg_mean_kernel(const float* __restrict__ x,
                     const int* __restrict__ lens,
                     float* __restrict__ out)
{
    const int b   = blockIdx.x >> 1;            // segment
    const int c   = blockIdx.x & (CCHUNKS - 1); // column chunk
    const int tid = threadIdx.x;
    const int lane = tid & 31;
    const int wid  = tid >> 5;

    // ---- segment start = sum(lens[0..b)): strided loads + shfl reduce ----
    __shared__ int ws[NWARPS];
    int psum = 0;
    for (int i = tid; i < b; i += THREADS) psum += __ldg(&lens[i]);
    #pragma unroll
    for (int off = 16; off > 0; off >>= 1)
        psum += __shfl_down_sync(0xFFFFFFFFu, psum, off);
    if (lane == 0) ws[wid] = psum;
    __syncthreads();
    int start = 0;
    #pragma unroll
    for (int w = 0; w < NWARPS; w++) start += ws[w];
    const int len = __ldg(&lens[b]);

    // ---- accumulate columns [16c, 16c+16) (float4 units) over all rows ----
    const float4* __restrict__ xv =
        reinterpret_cast<const float4*>(x) + (size_t)start * D4;
    const int csub = tid & (CF4 - 1);
    const int cg   = c * CF4 + csub;   // float4 column 0..31
    const int rg   = tid >> 4;         // row group 0..15

    float4 a0 = make_float4(0.f, 0.f, 0.f, 0.f);
    float4 a1 = a0, a2 = a0, a3 = a0;

    int r = rg;
    // 8 independent in-flight LDG.128 per thread, 128 rows/iter per CTA
    for (; r + 7 * RGROUPS < len; r += 8 * RGROUPS) {
        float4 v0 = xv[(size_t)(r + 0 * RGROUPS) * D4 + cg];
        float4 v1 = xv[(size_t)(r + 1 * RGROUPS) * D4 + cg];
        float4 v2 = xv[(size_t)(r + 2 * RGROUPS) * D4 + cg];
        float4 v3 = xv[(size_t)(r + 3 * RGROUPS) * D4 + cg];
        float4 v4 = xv[(size_t)(r + 4 * RGROUPS) * D4 + cg];
        float4 v5 = xv[(size_t)(r + 5 * RGROUPS) * D4 + cg];
        float4 v6 = xv[(size_t)(r + 6 * RGROUPS) * D4 + cg];
        float4 v7 = xv[(size_t)(r + 7 * RGROUPS) * D4 + cg];
        a0.x += v0.x; a0.y += v0.y; a0.z += v0.z; a0.w += v0.w;
        a1.x += v1.x; a1.y += v1.y; a1.z += v1.z; a1.w += v1.w;
        a2.x += v2.x; a2.y += v2.y; a2.z += v2.z; a2.w += v2.w;
        a3.x += v3.x; a3.y += v3.y; a3.z += v3.z; a3.w += v3.w;
        a0.x += v4.x; a0.y += v4.y; a0.z += v4.z; a0.w += v4.w;
        a1.x += v5.x; a1.y += v5.y; a1.z += v5.z; a1.w += v5.w;
        a2.x += v6.x; a2.y += v6.y; a2.z += v6.z; a2.w += v6.w;
        a3.x += v7.x; a3.y += v7.y; a3.z += v7.z; a3.w += v7.w;
    }
    for (; r < len; r += RGROUPS) {
        float4 v = xv[(size_t)r * D4 + cg];
        a0.x += v.x; a0.y += v.y; a0.z += v.z; a0.w += v.w;
    }
    a0.x += a1.x + a2.x + a3.x;
    a0.y += a1.y + a2.y + a3.y;
    a0.z += a1.z + a2.z + a3.z;
    a0.w += a1.w + a2.w + a3.w;

    // ---- reduce 16 row-groups per column in smem ----
    __shared__ float4 sred[RGROUPS][CF4];
    sred[rg][csub] = a0;
    __syncthreads();

    if (tid < CF4) {
        float4 s = sred[0][tid];
        #pragma unroll
        for (int g = 1; g < RGROUPS; g++) {
            float4 v = sred[g][tid];
            s.x += v.x; s.y += v.y; s.z += v.z; s.w += v.w;
        }
        const float inv = 1.0f / (float)len;
        float4 o = make_float4(s.x * inv, s.y * inv, s.z * inv, s.w * inv);
        reinterpret_cast<float4*>(out)[(size_t)b * D4 + c * CF4 + tid] = o;
    }
}

extern "C" void kernel_launch(void* const* d_in, const int* in_sizes, int n_in,
                              void* d_out, int out_size)
{
    const float* x    = (const float*)d_in[0];
    const int*   lens = (const int*)d_in[1];
    float*       out  = (float*)d_out;
    const int B = in_sizes[1];

    seg_mean_kernel<<<B * CCHUNKS, THREADS>>>(x, lens, out);
}

// round 15
// speedup vs baseline: 1.0488x; 1.0024x over previous
#include <cuda_runtime.h>

#define D 128
#define D4 (D / 4)              // 32 float4 per row
#define THREADS 256
#define NWARPS (THREADS / 32)   // 8
#define CCHUNKS 2               // column chunks per segment (64 cols each)
#define CF4 (D4 / CCHUNKS)      // 16 float4 columns per chunk
#define RGROUPS (THREADS / CF4) // 16 row groups

__global__ __launch_bounds__(THREADS, 4)
void seg_mean_kernel(const float* __restrict__ x,
                     const int* __restrict__ lens,
                     float* __restrict__ out)
{
    const int b   = blockIdx.x >> 1;            // segment
    const int c   = blockIdx.x & (CCHUNKS - 1); // column chunk
    const int tid = threadIdx.x;
    const int lane = tid & 31;
    const int wid  = tid >> 5;

    // ---- segment start = sum(lens[0..b)): strided loads + shfl reduce ----
    __shared__ int ws[NWARPS];
    int psum = 0;
    for (int i = tid; i < b; i += THREADS) psum += __ldg(&lens[i]);
    #pragma unroll
    for (int off = 16; off > 0; off >>= 1)
        psum += __shfl_down_sync(0xFFFFFFFFu, psum, off);
    if (lane == 0) ws[wid] = psum;
    __syncthreads();
    int start = 0;
    #pragma unroll
    for (int w = 0; w < NWARPS; w++) start += ws[w];
    const int len = __ldg(&lens[b]);

    // ---- accumulate columns [16c, 16c+16) (float4 units) over all rows ----
    const float4* __restrict__ xv =
        reinterpret_cast<const float4*>(x) + (size_t)start * D4;
    const int csub = tid & (CF4 - 1);
    const int cg   = c * CF4 + csub;   // float4 column 0..31
    const int rg   = tid >> 4;         // row group 0..15

    float4 a0 = make_float4(0.f, 0.f, 0.f, 0.f);
    float4 a1 = a0, a2 = a0, a3 = a0;

    int r = rg;
    // 8 independent in-flight LDG.128 per thread, 128 rows/iter per CTA
    for (; r + 7 * RGROUPS < len; r += 8 * RGROUPS) {
        float4 v0 = xv[(size_t)(r + 0 * RGROUPS) * D4 + cg];
        float4 v1 = xv[(size_t)(r + 1 * RGROUPS) * D4 + cg];
        float4 v2 = xv[(size_t)(r + 2 * RGROUPS) * D4 + cg];
        float4 v3 = xv[(size_t)(r + 3 * RGROUPS) * D4 + cg];
        float4 v4 = xv[(size_t)(r + 4 * RGROUPS) * D4 + cg];
        float4 v5 = xv[(size_t)(r + 5 * RGROUPS) * D4 + cg];
        float4 v6 = xv[(size_t)(r + 6 * RGROUPS) * D4 + cg];
        float4 v7 = xv[(size_t)(r + 7 * RGROUPS) * D4 + cg];
        a0.x += v0.x; a0.y += v0.y; a0.z += v0.z; a0.w += v0.w;
        a1.x += v1.x; a1.y += v1.y; a1.z += v1.z; a1.w += v1.w;
        a2.x += v2.x; a2.y += v2.y; a2.z += v2.z; a2.w += v2.w;
        a3.x += v3.x; a3.y += v3.y; a3.z += v3.z; a3.w += v3.w;
        a0.x += v4.x; a0.y += v4.y; a0.z += v4.z; a0.w += v4.w;
        a1.x += v5.x; a1.y += v5.y; a1.z += v5.z; a1.w += v5.w;
        a2.x += v6.x; a2.y += v6.y; a2.z += v6.z; a2.w += v6.w;
        a3.x += v7.x; a3.y += v7.y; a3.z += v7.z; a3.w += v7.w;
    }
    for (; r < len; r += RGROUPS) {
        float4 v = xv[(size_t)r * D4 + cg];
        a0.x += v.x; a0.y += v.y; a0.z += v.z; a0.w += v.w;
    }
    a0.x += a1.x + a2.x + a3.x;
    a0.y += a1.y + a2.y + a3.y;
    a0.z += a1.z + a2.z + a3.z;
    a0.w += a1.w + a2.w + a3.w;

    // ---- reduce 16 row-groups per column in smem ----
    __shared__ float4 sred[RGROUPS][CF4];
    sred[rg][csub] = a0;
    __syncthreads();

    if (tid < CF4) {
        float4 s = sred[0][tid];
        #pragma unroll
        for (int g = 1; g < RGROUPS; g++) {
            float4 v = sred[g][tid];
            s.x += v.x; s.y += v.y; s.z += v.z; s.w += v.w;
        }
        const float inv = 1.0f / (float)len;
        float4 o = make_float4(s.x * inv, s.y * inv, s.z * inv, s.w * inv);
        reinterpret_cast<float4*>(out)[(size_t)b * D4 + c * CF4 + tid] = o;
    }
}

extern "C" void kernel_launch(void* const* d_in, const int* in_sizes, int n_in,
                              void* d_out, int out_size)
{
    const float* x    = (const float*)d_in[0];
    const int*   lens = (const int*)d_in[1];
    float*       out  = (float*)d_out;
    const int B = in_sizes[1];

    seg_mean_kernel<<<B * CCHUNKS, THREADS>>>(x, lens, out);
}